// round 14
// baseline (speedup 1.0000x reference)
#include <cuda_runtime.h>
#include <cuda_fp16.h>
#include <cstdint>

#define NN 50000
#define NE 800000
#define KF 128      // IN_FEAT
#define NH 4        // heads
#define FD 16       // out feat per head
#define HF 64       // NH*FD
#define NEG 0.2f

// Scratch (device globals: allocation-free).
__device__ __half2 g_h16[NN * 32];  // h[n][64] as 32 half2 per node (fp16 storage)
__device__ float4  g_es[NN];        // e_src per node, 4 heads (fp32)
__device__ float4  g_ed[NN];        // e_dst per node, 4 heads (fp32)
__device__ int     g_is64;          // 1 if edge_index is int64, else 0 (int32)

// ---------------------------------------------------------------------------
// Kernel 1 (fused): out-zeroing + dtype probe + h = x@W + attention logits.
// h stored as fp16 (halves edge-phase gather traffic); logits stay fp32.
// ---------------------------------------------------------------------------
__global__ void __launch_bounds__(256) gemm_logits_kernel(
    const float* __restrict__ x,
    const float* __restrict__ W,
    const float* __restrict__ a,
    const void* __restrict__ ei_raw,
    float* __restrict__ out)
{
    const int tid = threadIdx.x;

    // ---- dtype probe (block 0 only; consumed by the NEXT kernel) ----
    if (blockIdx.x == 0) {
        const long long* e64 = (const long long*)ei_raw;
        bool ok = true;
        #pragma unroll
        for (int i = 0; i < 4; i++) {
            long long v = e64[tid * 4 + i];
            if (v < 0 || v >= NN) ok = false;
        }
        __shared__ int allok;
        if (tid == 0) allok = 1;
        __syncthreads();
        if (!ok) atomicAnd(&allok, 0);
        __syncthreads();
        if (tid == 0) g_is64 = allok;
    }

    // ---- zero the output (edge kernel reds into it; runs strictly after) ----
    {
        float4* o4 = reinterpret_cast<float4*>(out);
        const float4 z = make_float4(0.f, 0.f, 0.f, 0.f);
        for (int i = blockIdx.x * 256 + tid; i < NN * 16; i += gridDim.x * 256)
            o4[i] = z;
    }

    // ---- stage W in shared ----
    __shared__ float2 Ws[KF * 32];           // 32 KB; lane j owns cols 2j,2j+1
    __shared__ float4 xs[8][4][KF / 4];      // 16 KB; 4 x-rows per warp

    const float2* W2 = reinterpret_cast<const float2*>(W);
    for (int i = tid; i < KF * 32; i += 256) Ws[i] = W2[i];
    __syncthreads();

    const int lane = tid & 31;
    const int w    = tid >> 5;
    const int head = lane >> 3;              // cols 2*lane -> head = lane/8
    const int f0   = (2 * lane) & 15;

    const float as0 = a[head * 32 + f0];
    const float as1 = a[head * 32 + f0 + 1];
    const float ad0 = a[head * 32 + 16 + f0];
    const float ad1 = a[head * 32 + 17 + f0];

    const int ngroups = NN / 4;              // 12500 exactly
    const int nwarps  = gridDim.x * 8;

    for (int grp = blockIdx.x * 8 + w; grp < ngroups; grp += nwarps) {
        const int n0 = grp * 4;

        #pragma unroll
        for (int j = 0; j < 4; j++)
            xs[w][j][lane] = reinterpret_cast<const float4*>(x + (size_t)(n0 + j) * KF)[lane];
        __syncwarp();

        float ax0 = 0.f, ay0 = 0.f, ax1 = 0.f, ay1 = 0.f;
        float ax2 = 0.f, ay2 = 0.f, ax3 = 0.f, ay3 = 0.f;

        #pragma unroll
        for (int kk = 0; kk < KF / 4; kk++) {
            const float4 xv0 = xs[w][0][kk];
            const float4 xv1 = xs[w][1][kk];
            const float4 xv2 = xs[w][2][kk];
            const float4 xv3 = xs[w][3][kk];
            const float xk0[4] = {xv0.x, xv0.y, xv0.z, xv0.w};
            const float xk1[4] = {xv1.x, xv1.y, xv1.z, xv1.w};
            const float xk2[4] = {xv2.x, xv2.y, xv2.z, xv2.w};
            const float xk3[4] = {xv3.x, xv3.y, xv3.z, xv3.w};
            #pragma unroll
            for (int dk = 0; dk < 4; dk++) {
                const float2 wv = Ws[(kk * 4 + dk) * 32 + lane];
                ax0 = fmaf(xk0[dk], wv.x, ax0);  ay0 = fmaf(xk0[dk], wv.y, ay0);
                ax1 = fmaf(xk1[dk], wv.x, ax1);  ay1 = fmaf(xk1[dk], wv.y, ay1);
                ax2 = fmaf(xk2[dk], wv.x, ax2);  ay2 = fmaf(xk2[dk], wv.y, ay2);
                ax3 = fmaf(xk3[dk], wv.x, ax3);  ay3 = fmaf(xk3[dk], wv.y, ay3);
            }
        }

        // store h rows as fp16 (coalesced half2 per node: 128B per row)
        g_h16[(size_t)(n0 + 0) * 32 + lane] = __floats2half2_rn(ax0, ay0);
        g_h16[(size_t)(n0 + 1) * 32 + lane] = __floats2half2_rn(ax1, ay1);
        g_h16[(size_t)(n0 + 2) * 32 + lane] = __floats2half2_rn(ax2, ay2);
        g_h16[(size_t)(n0 + 3) * 32 + lane] = __floats2half2_rn(ax3, ay3);

        // logits computed from full-precision accumulators (exact softmax inputs)
        float psv[4], pdv[4];
        psv[0] = ax0 * as0 + ay0 * as1;  pdv[0] = ax0 * ad0 + ay0 * ad1;
        psv[1] = ax1 * as0 + ay1 * as1;  pdv[1] = ax1 * ad0 + ay1 * ad1;
        psv[2] = ax2 * as0 + ay2 * as1;  pdv[2] = ax2 * ad0 + ay2 * ad1;
        psv[3] = ax3 * as0 + ay3 * as1;  pdv[3] = ax3 * ad0 + ay3 * ad1;
        #pragma unroll
        for (int j = 0; j < 4; j++) {
            float ps = psv[j], pd = pdv[j];
            ps += __shfl_xor_sync(0xffffffffu, ps, 1);
            ps += __shfl_xor_sync(0xffffffffu, ps, 2);
            ps += __shfl_xor_sync(0xffffffffu, ps, 4);
            pd += __shfl_xor_sync(0xffffffffu, pd, 1);
            pd += __shfl_xor_sync(0xffffffffu, pd, 2);
            pd += __shfl_xor_sync(0xffffffffu, pd, 4);
            if ((lane & 7) == 0) {
                reinterpret_cast<float*>(g_es)[(n0 + j) * 4 + head] = ps;
                reinterpret_cast<float*>(g_ed)[(n0 + j) * 4 + head] = pd;
            }
        }
        __syncwarp();   // xs reused next iteration
    }
}

// ---------------------------------------------------------------------------
// Kernel 2: per-edge softmax-weighted gather + vectorized scatter-add.
// TWO edges per thread (e, e+NE/2); 16 lanes per edge; lane l owns cols
// [4l,4l+4) -> applied head h=l>>2. h gathered as fp16 (LDG.64 per lane).
// Cooperative quad softmax (lane computes head j=l&3; shfl trees).
// ---------------------------------------------------------------------------
__device__ __forceinline__ void red_add_v4(float* p, float4 v) {
    asm volatile("red.global.add.v4.f32 [%0], {%1, %2, %3, %4};"
                 :: "l"(p), "f"(v.x), "f"(v.y), "f"(v.z), "f"(v.w)
                 : "memory");
}

#define NE_HALF (NE / 2)

__global__ void __launch_bounds__(256) edge_scatter_kernel(
    const void* __restrict__ ei_raw,
    float* __restrict__ out)
{
    const int gtid = blockIdx.x * 256 + threadIdx.x;
    const int g = gtid >> 4;
    if (g >= NE_HALF) return;
    const int l  = gtid & 15;         // lane within edge group
    const int wl = threadIdx.x & 31;  // lane within warp (for shfl indexing)

    const int e0 = g;
    const int e1 = g + NE_HALF;

    int src0, dst0, src1, dst1;
    if (g_is64) {
        const long long* e64 = (const long long*)ei_raw;
        src0 = (int)e64[e0];  dst0 = (int)e64[NE + e0];
        src1 = (int)e64[e1];  dst1 = (int)e64[NE + e1];
    } else {
        const int* e32 = (const int*)ei_raw;
        src0 = e32[e0];  dst0 = e32[NE + e0];
        src1 = e32[e1];  dst1 = e32[NE + e1];
    }

    const int j = l & 3;              // head this lane computes softmax term for
    const int h = l >> 2;             // head this lane applies to features

    const float* esf = reinterpret_cast<const float*>(g_es);
    const float* edf = reinterpret_cast<const float*>(g_ed);

    // independent logit loads for both edges (4 scalar LDGs in flight)
    const float es0 = esf[src0 * 4 + j];
    const float ed0 = edf[dst0 * 4 + j];
    const float es1 = esf[src1 * 4 + j];
    const float ed1 = edf[dst1 * 4 + j];

    // independent fp16 gathers for both edges (2 LDG.64 in flight)
    const uint2 hp0 = *reinterpret_cast<const uint2*>(&g_h16[(size_t)src0 * 32 + 2 * l]);
    const uint2 hp1 = *reinterpret_cast<const uint2*>(&g_h16[(size_t)src1 * 32 + 2 * l]);

    float z0 = es0 + ed0;  z0 = z0 > 0.f ? z0 : NEG * z0;
    float z1 = es1 + ed1;  z1 = z1 > 0.f ? z1 : NEG * z1;

    const unsigned m32 = 0xffffffffu;
    // interleaved quad max trees
    float mx0 = z0, mx1 = z1;
    mx0 = fmaxf(mx0, __shfl_xor_sync(m32, mx0, 1));
    mx1 = fmaxf(mx1, __shfl_xor_sync(m32, mx1, 1));
    mx0 = fmaxf(mx0, __shfl_xor_sync(m32, mx0, 2));
    mx1 = fmaxf(mx1, __shfl_xor_sync(m32, mx1, 2));
    const float p0 = __expf(z0 - mx0);
    const float p1 = __expf(z1 - mx1);
    float s0 = p0, s1 = p1;
    s0 += __shfl_xor_sync(m32, s0, 1);
    s1 += __shfl_xor_sync(m32, s1, 1);
    s0 += __shfl_xor_sync(m32, s0, 2);
    s1 += __shfl_xor_sync(m32, s1, 2);

    const int srclane = (wl & ~3) | h;
    const float ph0 = __shfl_sync(m32, p0, srclane);
    const float ph1 = __shfl_sync(m32, p1, srclane);
    const float a0 = ph0 / s0;
    const float a1 = ph1 / s1;

    // unpack fp16 -> fp32 and scale
    const float2 h0a = __half22float2(*reinterpret_cast<const __half2*>(&hp0.x));
    const float2 h0b = __half22float2(*reinterpret_cast<const __half2*>(&hp0.y));
    const float2 h1a = __half22float2(*reinterpret_cast<const __half2*>(&hp1.x));
    const float2 h1b = __half22float2(*reinterpret_cast<const __half2*>(&hp1.y));

    float4 v0 = make_float4(a0 * h0a.x, a0 * h0a.y, a0 * h0b.x, a0 * h0b.y);
    float4 v1 = make_float4(a1 * h1a.x, a1 * h1a.y, a1 * h1b.x, a1 * h1b.y);

    red_add_v4(out + (size_t)dst0 * HF + 4 * l, v0);
    red_add_v4(out + (size_t)dst1 * HF + 4 * l, v1);
}

// ---------------------------------------------------------------------------
extern "C" void kernel_launch(void* const* d_in, const int* in_sizes, int n_in,
                              void* d_out, int out_size)
{
    const float* x  = (const float*)d_in[0];
    const void*  ei = (const void*)d_in[1];
    const float* W  = (const float*)d_in[2];
    const float* a  = (const float*)d_in[3];
    float* out = (float*)d_out;

    gemm_logits_kernel<<<592, 256>>>(x, W, a, ei, out);

    const int nthreads = NE_HALF * 16;
    edge_scatter_kernel<<<(nthreads + 255) / 256, 256>>>(ei, out);

    (void)in_sizes; (void)n_in; (void)out_size;
}

// round 17
// speedup vs baseline: 1.3429x; 1.3429x over previous
#include <cuda_runtime.h>
#include <cuda_bf16.h>
#include <cstdint>

#define NN 50000
#define NE 800000
#define KF 128      // IN_FEAT
#define NH 4        // heads
#define FD 16       // out feat per head
#define HF 64       // NH*FD
#define NEG 0.2f

// Scratch (device globals: allocation-free). float4 typing guarantees 16B alignment.
__device__ float4 g_h[NN * 16];   // h[n][64] as 16 float4 per node
__device__ float4 g_es[NN];       // e_src per node, 4 heads
__device__ float4 g_ed[NN];       // e_dst per node, 4 heads
__device__ int    g_is64;         // 1 if edge_index is int64, else 0 (int32)

// ---------------------------------------------------------------------------
// Kernel 1 (fused): out-zeroing + dtype probe + h = x@W + attention logits.
// ---------------------------------------------------------------------------
__global__ void __launch_bounds__(256) gemm_logits_kernel(
    const float* __restrict__ x,
    const float* __restrict__ W,
    const float* __restrict__ a,
    const void* __restrict__ ei_raw,
    float* __restrict__ out)
{
    const int tid = threadIdx.x;

    // ---- dtype probe (block 0 only; consumed by the NEXT kernel) ----
    if (blockIdx.x == 0) {
        const long long* e64 = (const long long*)ei_raw;
        bool ok = true;
        #pragma unroll
        for (int i = 0; i < 4; i++) {
            long long v = e64[tid * 4 + i];
            if (v < 0 || v >= NN) ok = false;
        }
        __shared__ int allok;
        if (tid == 0) allok = 1;
        __syncthreads();
        if (!ok) atomicAnd(&allok, 0);
        __syncthreads();
        if (tid == 0) g_is64 = allok;
    }

    // ---- zero the output (edge kernel reds into it; runs strictly after) ----
    {
        float4* o4 = reinterpret_cast<float4*>(out);
        const float4 z = make_float4(0.f, 0.f, 0.f, 0.f);
        for (int i = blockIdx.x * 256 + tid; i < NN * 16; i += gridDim.x * 256)
            o4[i] = z;
    }

    // ---- stage W in shared ----
    __shared__ float2 Ws[KF * 32];           // 32 KB; lane j owns cols 2j,2j+1
    __shared__ float4 xs[8][4][KF / 4];      // 16 KB; 4 x-rows per warp

    const float2* W2 = reinterpret_cast<const float2*>(W);
    for (int i = tid; i < KF * 32; i += 256) Ws[i] = W2[i];
    __syncthreads();

    const int lane = tid & 31;
    const int w    = tid >> 5;
    const int head = lane >> 3;              // cols 2*lane -> head = lane/8
    const int f0   = (2 * lane) & 15;

    const float as0 = a[head * 32 + f0];
    const float as1 = a[head * 32 + f0 + 1];
    const float ad0 = a[head * 32 + 16 + f0];
    const float ad1 = a[head * 32 + 17 + f0];

    const int ngroups = NN / 4;              // 12500 exactly
    const int nwarps  = gridDim.x * 8;

    for (int grp = blockIdx.x * 8 + w; grp < ngroups; grp += nwarps) {
        const int n0 = grp * 4;

        #pragma unroll
        for (int j = 0; j < 4; j++)
            xs[w][j][lane] = reinterpret_cast<const float4*>(x + (size_t)(n0 + j) * KF)[lane];
        __syncwarp();

        float ax0 = 0.f, ay0 = 0.f, ax1 = 0.f, ay1 = 0.f;
        float ax2 = 0.f, ay2 = 0.f, ax3 = 0.f, ay3 = 0.f;

        #pragma unroll
        for (int kk = 0; kk < KF / 4; kk++) {
            const float4 xv0 = xs[w][0][kk];
            const float4 xv1 = xs[w][1][kk];
            const float4 xv2 = xs[w][2][kk];
            const float4 xv3 = xs[w][3][kk];
            const float xk0[4] = {xv0.x, xv0.y, xv0.z, xv0.w};
            const float xk1[4] = {xv1.x, xv1.y, xv1.z, xv1.w};
            const float xk2[4] = {xv2.x, xv2.y, xv2.z, xv2.w};
            const float xk3[4] = {xv3.x, xv3.y, xv3.z, xv3.w};
            #pragma unroll
            for (int dk = 0; dk < 4; dk++) {
                const float2 wv = Ws[(kk * 4 + dk) * 32 + lane];
                ax0 = fmaf(xk0[dk], wv.x, ax0);  ay0 = fmaf(xk0[dk], wv.y, ay0);
                ax1 = fmaf(xk1[dk], wv.x, ax1);  ay1 = fmaf(xk1[dk], wv.y, ay1);
                ax2 = fmaf(xk2[dk], wv.x, ax2);  ay2 = fmaf(xk2[dk], wv.y, ay2);
                ax3 = fmaf(xk3[dk], wv.x, ax3);  ay3 = fmaf(xk3[dk], wv.y, ay3);
            }
        }

        float2* h2 = reinterpret_cast<float2*>(g_h);
        h2[(size_t)(n0 + 0) * 32 + lane] = make_float2(ax0, ay0);
        h2[(size_t)(n0 + 1) * 32 + lane] = make_float2(ax1, ay1);
        h2[(size_t)(n0 + 2) * 32 + lane] = make_float2(ax2, ay2);
        h2[(size_t)(n0 + 3) * 32 + lane] = make_float2(ax3, ay3);

        float psv[4], pdv[4];
        psv[0] = ax0 * as0 + ay0 * as1;  pdv[0] = ax0 * ad0 + ay0 * ad1;
        psv[1] = ax1 * as0 + ay1 * as1;  pdv[1] = ax1 * ad0 + ay1 * ad1;
        psv[2] = ax2 * as0 + ay2 * as1;  pdv[2] = ax2 * ad0 + ay2 * ad1;
        psv[3] = ax3 * as0 + ay3 * as1;  pdv[3] = ax3 * ad0 + ay3 * ad1;
        #pragma unroll
        for (int j = 0; j < 4; j++) {
            float ps = psv[j], pd = pdv[j];
            ps += __shfl_xor_sync(0xffffffffu, ps, 1);
            ps += __shfl_xor_sync(0xffffffffu, ps, 2);
            ps += __shfl_xor_sync(0xffffffffu, ps, 4);
            pd += __shfl_xor_sync(0xffffffffu, pd, 1);
            pd += __shfl_xor_sync(0xffffffffu, pd, 2);
            pd += __shfl_xor_sync(0xffffffffu, pd, 4);
            if ((lane & 7) == 0) {
                reinterpret_cast<float*>(g_es)[(n0 + j) * 4 + head] = ps;
                reinterpret_cast<float*>(g_ed)[(n0 + j) * 4 + head] = pd;
            }
        }
        __syncwarp();   // xs reused next iteration
    }
}

// ---------------------------------------------------------------------------
// Kernel 2: per-edge softmax-weighted gather + vectorized scatter-add.
// FOUR edges per thread (e + k*NE/4) to maximize memory-level parallelism:
// all index/logit/gather loads for the 4 edges are independent and
// front-batched. 16 lanes per edge; lane l owns cols [4l,4l+4); applied
// head h=l>>2. Cooperative quad softmax (lane computes head j=l&3).
// ---------------------------------------------------------------------------
__device__ __forceinline__ void red_add_v4(float* p, float4 v) {
    asm volatile("red.global.add.v4.f32 [%0], {%1, %2, %3, %4};"
                 :: "l"(p), "f"(v.x), "f"(v.y), "f"(v.z), "f"(v.w)
                 : "memory");
}

#define NE_Q (NE / 4)

__global__ void __launch_bounds__(256) edge_scatter_kernel(
    const void* __restrict__ ei_raw,
    float* __restrict__ out)
{
    const int gtid = blockIdx.x * 256 + threadIdx.x;
    const int g = gtid >> 4;
    if (g >= NE_Q) return;
    const int l  = gtid & 15;         // lane within edge group
    const int wl = threadIdx.x & 31;  // lane within warp (for shfl indexing)

    int src[4], dst[4];
    if (g_is64) {
        const long long* e64 = (const long long*)ei_raw;
        #pragma unroll
        for (int k = 0; k < 4; k++) {
            src[k] = (int)e64[g + k * NE_Q];
            dst[k] = (int)e64[NE + g + k * NE_Q];
        }
    } else {
        const int* e32 = (const int*)ei_raw;
        #pragma unroll
        for (int k = 0; k < 4; k++) {
            src[k] = e32[g + k * NE_Q];
            dst[k] = e32[NE + g + k * NE_Q];
        }
    }

    const int j = l & 3;              // head this lane computes softmax term for
    const int h = l >> 2;             // head this lane applies to features

    const float* esf = reinterpret_cast<const float*>(g_es);
    const float* edf = reinterpret_cast<const float*>(g_ed);

    // front-batched independent loads: 8 scalar logit LDGs + 4 LDG.128 gathers
    float es[4], ed[4];
    float4 hv[4];
    #pragma unroll
    for (int k = 0; k < 4; k++) es[k] = esf[src[k] * 4 + j];
    #pragma unroll
    for (int k = 0; k < 4; k++) ed[k] = edf[dst[k] * 4 + j];
    #pragma unroll
    for (int k = 0; k < 4; k++) hv[k] = g_h[(size_t)src[k] * 16 + l];

    const unsigned m32 = 0xffffffffu;

    float z[4], p[4], s[4];
    #pragma unroll
    for (int k = 0; k < 4; k++) {
        z[k] = es[k] + ed[k];
        z[k] = z[k] > 0.f ? z[k] : NEG * z[k];
    }

    // interleaved quad max trees (4 edges in flight)
    float mx[4];
    #pragma unroll
    for (int k = 0; k < 4; k++) mx[k] = z[k];
    #pragma unroll
    for (int k = 0; k < 4; k++) mx[k] = fmaxf(mx[k], __shfl_xor_sync(m32, mx[k], 1));
    #pragma unroll
    for (int k = 0; k < 4; k++) mx[k] = fmaxf(mx[k], __shfl_xor_sync(m32, mx[k], 2));
    #pragma unroll
    for (int k = 0; k < 4; k++) p[k] = __expf(z[k] - mx[k]);
    #pragma unroll
    for (int k = 0; k < 4; k++) s[k] = p[k];
    #pragma unroll
    for (int k = 0; k < 4; k++) s[k] += __shfl_xor_sync(m32, s[k], 1);
    #pragma unroll
    for (int k = 0; k < 4; k++) s[k] += __shfl_xor_sync(m32, s[k], 2);

    const int srclane = (wl & ~3) | h;
    #pragma unroll
    for (int k = 0; k < 4; k++) {
        const float ph = __shfl_sync(m32, p[k], srclane);
        const float al = ph / s[k];
        float4 v = make_float4(al * hv[k].x, al * hv[k].y, al * hv[k].z, al * hv[k].w);
        red_add_v4(out + (size_t)dst[k] * HF + 4 * l, v);
    }
}

// ---------------------------------------------------------------------------
extern "C" void kernel_launch(void* const* d_in, const int* in_sizes, int n_in,
                              void* d_out, int out_size)
{
    const float* x  = (const float*)d_in[0];
    const void*  ei = (const void*)d_in[1];
    const float* W  = (const float*)d_in[2];
    const float* a  = (const float*)d_in[3];
    float* out = (float*)d_out;

    gemm_logits_kernel<<<592, 256>>>(x, W, a, ei, out);

    const int nthreads = NE_Q * 16;
    edge_scatter_kernel<<<(nthreads + 255) / 256, 256>>>(ei, out);

    (void)in_sizes; (void)n_in; (void)out_size;
}